// round 4
// baseline (speedup 1.0000x reference)
#include <cuda_runtime.h>
#include <cstdint>

// CostVolume: cost[b,i,h,x] = (1/128) sum_c L[b,c,h,x]*R[b,c,h,x-i], 0 for x<i.
// b=8 c=128 h=96 w=320, 48 disparities, fp32.
// FFMA2 (fma.rn.f32x2) kernel. CTA = 1 unit (b,h,x0-tile of 128) = 2 warps.
// Thread tile: 16 x (8 packed pairs) x 6 i = 48 ull accumulators (96 regs).

typedef unsigned long long ull;

#define BB 8
#define CH 128
#define HH 96
#define WW 320
#define MAXD 48
#define PLANE (HH*WW)

#define CC 8                         // channels per chunk
#define NCHUNK (CH/CC)               // 16
#define LROW 128                     // L floats per channel row
#define RROW 176                     // R floats per channel row [x0-48, x0+128)
#define STAGE_FLOATS (CC*(LROW+RROW))      // 2432
#define STAGE_BYTES (STAGE_FLOATS*4)       // 9728
#define SMEM_TOTAL (2*STAGE_BYTES)         // 19456
#define NLINES (STAGE_BYTES/16)            // 608 16B lines per stage

__device__ __forceinline__ uint32_t smem_u32(const void* p){
    uint32_t a;
    asm("{ .reg .u64 t; cvta.to.shared.u64 t, %1; cvt.u32.u64 %0, t; }" : "=r"(a) : "l"(p));
    return a;
}
__device__ __forceinline__ void cp16(uint32_t dst, const void* src, uint32_t sz){
    asm volatile("cp.async.ca.shared.global [%0], [%1], 16, %2;"
                 :: "r"(dst), "l"(src), "r"(sz) : "memory");
}
__device__ __forceinline__ ull pack2(float lo, float hi){
    ull d; asm("mov.b64 %0, {%1,%2};" : "=l"(d) : "f"(lo), "f"(hi)); return d;
}
__device__ __forceinline__ void unpack2(ull v, float& lo, float& hi){
    asm("mov.b64 {%0,%1}, %2;" : "=f"(lo), "=f"(hi) : "l"(v));
}
__device__ __forceinline__ void fma2(ull& a, ull x, ull y){
    asm("fma.rn.f32x2 %0, %1, %2, %0;" : "+l"(a) : "l"(x), "l"(y));
}
__device__ __forceinline__ ull mul2(ull x, ull y){
    ull d; asm("mul.rn.f32x2 %0, %1, %2;" : "=l"(d) : "l"(x), "l"(y)); return d;
}

__global__ __launch_bounds__(64, 5)
void costvol_v4_kernel(const float* __restrict__ L,
                       const float* __restrict__ R,
                       float* __restrict__ out)
{
    extern __shared__ float smem[];
    const uint32_t sbase = smem_u32(smem);

    const int tid  = threadIdx.x;       // 0..63
    const int w01  = tid >> 5;          // warp in unit: i-half
    const int lane = tid & 31;
    const int xq = lane >> 2;           // 0..7
    const int ig = lane & 3;            // 0..3

    const int unit = blockIdx.x;        // 2304 units
    const int xt = unit % 3;
    const int bh = unit / 3;
    const int h  = bh % HH;
    const int b  = bh / HH;
    const int x0 = xt * 96;             // tiles {0,96,192}, width 128; overlap rows
                                        // recompute bitwise-identical values

    const float* Lbh = L + ((size_t)b * CH * HH + h) * WW;
    const float* Rbh = R + ((size_t)b * CH * HH + h) * WW;

    const int X  = x0 + 16 * xq;        // first x of this thread
    const int i0 = 24 * w01 + 6 * ig;   // first disparity (6 per thread)
    const int base = 48 + 16 * xq - i0; // R-row offset of (x=X, i=i0); even, >= 6

    ull acc[6][8];
    #pragma unroll
    for (int a = 0; a < 6; a++)
        #pragma unroll
        for (int u = 0; u < 8; u++) acc[a][u] = 0ULL;

    // ---- cooperative async load of one chunk: 608 x 16B, both warps ----
    auto issue = [&](int k){
        const int c0 = k * CC;
        const uint32_t sb = sbase + (k & 1) * STAGE_BYTES;
        #pragma unroll
        for (int it = 0; it < 10; it++){
            int idx = tid + it * 64;
            if (idx < NLINES){
                int cc = idx / 76;
                int j  = idx - cc * 76;
                const float* gp;
                uint32_t dst, sz = 16;
                if (j < 32){                        // L: 32 lines per channel
                    gp  = Lbh + (size_t)(c0 + cc) * PLANE + x0 + 4 * j;
                    dst = sb + cc * (LROW * 4) + 16 * j;
                } else {                            // R: 44 lines per channel
                    int jr = j - 32;
                    int xr = x0 - 48 + 4 * jr;
                    int xs = xr < 0 ? 0 : xr;
                    gp  = Rbh + (size_t)(c0 + cc) * PLANE + xs;
                    sz  = (xr >= 0) ? 16u : 0u;     // zero-fill x' < 0
                    dst = sb + CC * (LROW * 4) + cc * (RROW * 4) + 16 * jr;
                }
                cp16(dst, gp, sz);
            }
        }
    };

    // ---- compute one chunk ----
    auto compute = [&](int k){
        const float* st = smem + (k & 1) * STAGE_FLOATS;
        #pragma unroll
        for (int cc = 0; cc < CC; cc++){
            const float* Lr = st + cc * LROW + 16 * xq;
            const float* Rr = st + CC * LROW + cc * RROW;

            // L pairs: 4 x LDS.128 -> 8 aligned ull pairs
            ull l2[8];
            #pragma unroll
            for (int t = 0; t < 4; t++){
                ulonglong2 v = *(const ulonglong2*)(Lr + 4 * t);
                l2[2*t]   = v.x;
                l2[2*t+1] = v.y;
            }
            // R pairs: q[j] = (r[base-6+2j], r[base-6+2j+1]), j=0..10 (LDS.64)
            ull q[11];
            #pragma unroll
            for (int j = 0; j < 11; j++)
                q[j] = *(const ull*)(Rr + base - 6 + 2 * j);

            // even disparities a=2a2: operand = q[u+3-a2] directly (no packs)
            #pragma unroll
            for (int a2 = 0; a2 < 3; a2++)
                #pragma unroll
                for (int u = 0; u < 8; u++)
                    fma2(acc[2*a2][u], l2[u], q[u + 3 - a2]);

            // odd disparities: m[jm] = (hi(q[jm]), lo(q[jm+1])), jm=0..9
            float qx[11], qy[11];
            #pragma unroll
            for (int j = 0; j < 11; j++) unpack2(q[j], qx[j], qy[j]);
            ull m[10];
            #pragma unroll
            for (int jm = 0; jm < 10; jm++) m[jm] = pack2(qy[jm], qx[jm+1]);

            #pragma unroll
            for (int ao = 0; ao < 3; ao++)
                #pragma unroll
                for (int u = 0; u < 8; u++)
                    fma2(acc[2*ao+1][u], l2[u], m[u + 2 - ao]);
        }
    };

    // ---- pipelined main loop (double-buffered, CTA-synced) ----
    issue(0);
    asm volatile("cp.async.commit_group;" ::: "memory");
    #pragma unroll 1
    for (int k = 0; k < NCHUNK; k++){
        if (k + 1 < NCHUNK){
            issue(k + 1);
            asm volatile("cp.async.commit_group;" ::: "memory");
            asm volatile("cp.async.wait_group 1;" ::: "memory");
        } else {
            asm volatile("cp.async.wait_group 0;" ::: "memory");
        }
        __syncthreads();      // stage k complete (both warps' lines)
        compute(k);
        __syncthreads();      // stage k consumed before issue(k+2) overwrites
    }

    // ---- epilogue: scale by 1/128, 16B coalesced stores ----
    const ull s2 = pack2(1.0f/128.0f, 1.0f/128.0f);
    #pragma unroll
    for (int a = 0; a < 6; a++){
        const int i = i0 + a;
        float* dst = out + (((size_t)b * MAXD + i) * HH + h) * WW + X;
        #pragma unroll
        for (int t = 0; t < 4; t++){
            ulonglong2 v;
            v.x = mul2(acc[a][2*t],     s2);
            v.y = mul2(acc[a][2*t + 1], s2);
            *(ulonglong2*)(dst + 4 * t) = v;
        }
    }
}

extern "C" void kernel_launch(void* const* d_in, const int* in_sizes, int n_in,
                              void* d_out, int out_size)
{
    const float* L = (const float*)d_in[0];
    const float* R = (const float*)d_in[1];
    float* out = (float*)d_out;

    cudaFuncSetAttribute(costvol_v4_kernel,
                         cudaFuncAttributeMaxDynamicSharedMemorySize, SMEM_TOTAL);
    dim3 grid(BB * HH * 3);   // 2304 CTAs, one unit each
    costvol_v4_kernel<<<grid, 64, SMEM_TOTAL>>>(L, R, out);
}